// round 11
// baseline (speedup 1.0000x reference)
#include <cuda_runtime.h>

#define Bn 8
#define Dn 192
#define Ln 4096
#define Nn 16
#define Rn 6
#define Cn 38
#define Kn 4
#define NC 32
#define Lc 128

// scratch (allocation-free device globals); DU padded 4 steps for prefetch ring
__device__ float g_DU[(size_t)Bn*Kn*Ln*Dn*2 + Dn*8];
__device__ float g_B [(size_t)Bn*Kn*Ln*Nn];
__device__ float g_C [(size_t)Bn*Kn*Ln*Nn];
__device__ float g_ym[(size_t)Bn*Ln*Dn];             // merged y (b,l,d)
__device__ float g_hend[(size_t)Bn*Kn*NC*Dn*Nn];
__device__ float g_S[(size_t)Bn*Kn*NC*Dn];

__device__ __forceinline__ float ex2f(float x){
    float r; asm("ex2.approx.ftz.f32 %0, %1;" : "=f"(r) : "f"(x)); return r;
}
__device__ __forceinline__ float lg2f(float x){
    float r; asm("lg2.approx.ftz.f32 %0, %1;" : "=f"(r) : "f"(x)); return r;
}

// ---------------------------------------------------------------------------
// Kernel A: cross-scan gather + x_proj + dt_proj + softplus. (R8 config)
// ---------------------------------------------------------------------------
__global__ __launch_bounds__(256, 3) void proj_kernel(
    const float* __restrict__ x, const float* __restrict__ xpw,
    const float* __restrict__ dtw, const float* __restrict__ dtb)
{
    __shared__ float xt[Dn*64];        // xt[d][j], j=0..63
    __shared__ float dts_s[Rn][64];
    __shared__ float sB[64][16];
    __shared__ float sC[64][16];

    const int bid = blockIdx.x;        // 2048 = 8*4*64
    const int t   = bid & 63;
    const int k   = (bid >> 6) & 3;
    const int b   = bid >> 8;
    const int tid = threadIdx.x;

    int p0, pstep;
    if (k == 2) { p0 = 4095 - t*64; pstep = -1; }
    else        { p0 = t*64;        pstep = 1;  }

    const float* xb = x + (size_t)b*Dn*Ln;
    for (int idx = tid; idx < Dn*64; idx += 256) {
        int d = idx >> 6, j = idx & 63;
        xt[idx] = xb[(size_t)d*Ln + p0 + j*pstep];
    }
    __syncthreads();

    auto lof = [&](int j) -> int {
        if (k == 1) return j*64 + t;
        if (k == 3) return 4095 - j*64 - t;
        return t*64 + j;
    };

    {
        const int j = tid & 31;        // positions j and j+32
        const int w = tid >> 5;

        float acc[5][2];
        #pragma unroll
        for (int m = 0; m < 5; m++) { acc[m][0] = 0.f; acc[m][1] = 0.f; }
        const float4* wp[5];
        #pragma unroll
        for (int m = 0; m < 5; m++) {
            int c = w + 8*m; if (c > Cn-1) c = Cn-1;
            wp[m] = (const float4*)(xpw + (size_t)(k*Cn + c)*Dn);
        }
        #pragma unroll 2
        for (int i = 0; i < Dn/4; i++) {
            float a0 = xt[(4*i+0)*64 + j],  b0 = xt[(4*i+0)*64 + j+32];
            float a1 = xt[(4*i+1)*64 + j],  b1 = xt[(4*i+1)*64 + j+32];
            float a2 = xt[(4*i+2)*64 + j],  b2 = xt[(4*i+2)*64 + j+32];
            float a3 = xt[(4*i+3)*64 + j],  b3 = xt[(4*i+3)*64 + j+32];
            #pragma unroll
            for (int m = 0; m < 5; m++) {
                float4 wv = wp[m][i];
                acc[m][0] = fmaf(wv.x, a0, acc[m][0]);
                acc[m][1] = fmaf(wv.x, b0, acc[m][1]);
                acc[m][0] = fmaf(wv.y, a1, acc[m][0]);
                acc[m][1] = fmaf(wv.y, b1, acc[m][1]);
                acc[m][0] = fmaf(wv.z, a2, acc[m][0]);
                acc[m][1] = fmaf(wv.z, b2, acc[m][1]);
                acc[m][0] = fmaf(wv.w, a3, acc[m][0]);
                acc[m][1] = fmaf(wv.w, b3, acc[m][1]);
            }
        }
        #pragma unroll
        for (int m = 0; m < 5; m++) {
            int c = w + 8*m;
            if (c < Rn) { dts_s[c][j] = acc[m][0]; dts_s[c][j+32] = acc[m][1]; }
            else if (c < Cn) {
                int n = c - Rn;
                if (n < Nn) { sB[j][n] = acc[m][0]; sB[j+32][n] = acc[m][1]; }
                else        { int nn = n - Nn;
                              sC[j][nn] = acc[m][0]; sC[j+32][nn] = acc[m][1]; }
            }
        }
    }
    __syncthreads();

    {
        const int pos = tid >> 2, nq = tid & 3;
        const size_t base = ((size_t)(b*Kn + k)*Ln + lof(pos))*(size_t)Nn + 4*nq;
        *(float4*)&g_B[base] = *(const float4*)&sB[pos][4*nq];
        *(float4*)&g_C[base] = *(const float4*)&sC[pos][4*nq];
    }

    for (int idx = tid; idx < Dn*64; idx += 256) {
        int d = idx % Dn, j = idx / Dn;
        float acc = dtb[k*Dn + d];
        #pragma unroll
        for (int r = 0; r < Rn; r++) acc = fmaf(dts_s[r][j], dtw[(k*Dn + d)*Rn + r], acc);
        float e = ex2f(acc * 1.4426950408889634f);
        float sp = 0.6931471805599453f * lg2f(1.f + e);
        if (acc > 20.f) sp = acc;
        float u = xt[d*64 + j];
        int l = lof(j);
        size_t o = ((size_t)(b*Kn + k)*Ln + l)*Dn + d;
        ((float2*)g_DU)[o] = make_float2(sp, u);
    }
}

// ---------------------------------------------------------------------------
// Scan pass 1: lane=channel, A/h/dA in regs, ring-4 DU prefetch, hoisted EX2.
// ---------------------------------------------------------------------------
__global__ __launch_bounds__(192, 4) void scan_p1(const float* __restrict__ A_logs)
{
    __shared__ float4 sB[Lc*4];
    const int bk = blockIdx.x >> 5;
    const int c  = blockIdx.x & 31;
    const int d  = threadIdx.x;
    const int k  = bk & 3;

    const float4* gb = (const float4*)(g_B + ((size_t)bk*Ln + (size_t)c*Lc)*16);
    for (int i = d; i < Lc*4; i += 192) sB[i] = gb[i];
    __syncthreads();

    float A[16];
    {
        const float4* al = (const float4*)(A_logs + (size_t)(k*Dn + d)*16);
        #pragma unroll
        for (int m = 0; m < 4; m++) {
            float4 v = al[m];
            A[4*m+0] = -expf(v.x) * 1.4426950408889634f;
            A[4*m+1] = -expf(v.y) * 1.4426950408889634f;
            A[4*m+2] = -expf(v.z) * 1.4426950408889634f;
            A[4*m+3] = -expf(v.w) * 1.4426950408889634f;
        }
    }

    float h[16];
    #pragma unroll
    for (int n = 0; n < 16; n++) h[n] = 0.f;
    float S = 0.f;

    const float2* du = ((const float2*)g_DU) + ((size_t)bk*Ln + (size_t)c*Lc)*Dn + d;
    float2 ring[4];
    #pragma unroll
    for (int i = 0; i < 4; i++) ring[i] = du[(size_t)i*Dn];
    du += 4*Dn;

    float dA[16];
    #pragma unroll
    for (int n = 0; n < 16; n++) dA[n] = ex2f(ring[0].x * A[n]);

    #pragma unroll 4
    for (int t = 0; t < Lc; t++) {
        float2 cur = ring[t & 3];
        ring[t & 3] = du[0]; du += Dn;
        float dt = cur.x, dtu = dt*cur.y;
        S += dt;
        #pragma unroll
        for (int m = 0; m < 4; m++) {
            float4 q = sB[t*4 + m];
            h[4*m+0] = fmaf(dA[4*m+0], h[4*m+0], dtu*q.x);
            h[4*m+1] = fmaf(dA[4*m+1], h[4*m+1], dtu*q.y);
            h[4*m+2] = fmaf(dA[4*m+2], h[4*m+2], dtu*q.z);
            h[4*m+3] = fmaf(dA[4*m+3], h[4*m+3], dtu*q.w);
        }
        float dtn = ring[(t+1) & 3].x;
        #pragma unroll
        for (int n = 0; n < 16; n++) dA[n] = ex2f(dtn * A[n]);
    }

    float4* out = (float4*)(g_hend + (((size_t)bk*NC + c)*Dn + d)*16);
    #pragma unroll
    for (int m = 0; m < 4; m++) out[m] = make_float4(h[4*m], h[4*m+1], h[4*m+2], h[4*m+3]);
    g_S[((size_t)bk*NC + c)*Dn + d] = S;
}

// ---------------------------------------------------------------------------
// Scan mid: chain chunk summaries -> exclusive h_init prefix (in place).
// ---------------------------------------------------------------------------
__global__ __launch_bounds__(256) void scan_mid(const float* __restrict__ A_logs)
{
    int gid = blockIdx.x*256 + threadIdx.x;
    if (gid >= 32*Dn*Nn) return;
    int n  = gid & 15;
    int d  = (gid >> 4) % Dn;
    int bk = gid / (Dn*16);
    int k  = bk & 3;
    float A = -expf(A_logs[(size_t)(k*Dn + d)*16 + n]) * 1.4426950408889634f;
    float h = 0.f;
    for (int c = 0; c < NC; c++) {
        size_t o = (((size_t)bk*NC + c)*Dn + d)*16 + n;
        float hend = g_hend[o];
        float S = g_S[((size_t)bk*NC + c)*Dn + d];
        g_hend[o] = h;
        h = fmaf(ex2f(A*S), h, hend);
    }
}

// ---------------------------------------------------------------------------
// Scan pass 2 (per direction k, launched 4x sequentially): rescan from h_init,
// accumulate y directly at the canonical merged position in g_ym.
// k=0 stores, k>0 read-modify-write (race-free: one block per position per k;
// directions ordered by launch boundaries -> deterministic sum order).
// ---------------------------------------------------------------------------
__global__ __launch_bounds__(192, 4) void scan_p2(
    const float* __restrict__ A_logs, const float* __restrict__ Ds, int k)
{
    __shared__ float4 sB[Lc*4];
    __shared__ float4 sC[Lc*4];
    const int b  = blockIdx.x >> 5;
    const int c  = blockIdx.x & 31;
    const int d  = threadIdx.x;
    const int bk = b*Kn + k;

    const float4* gb = (const float4*)(g_B + ((size_t)bk*Ln + (size_t)c*Lc)*16);
    const float4* gc = (const float4*)(g_C + ((size_t)bk*Ln + (size_t)c*Lc)*16);
    for (int i = d; i < Lc*4; i += 192) { sB[i] = gb[i]; sC[i] = gc[i]; }
    __syncthreads();

    float A[16];
    {
        const float4* al = (const float4*)(A_logs + (size_t)(k*Dn + d)*16);
        #pragma unroll
        for (int m = 0; m < 4; m++) {
            float4 v = al[m];
            A[4*m+0] = -expf(v.x) * 1.4426950408889634f;
            A[4*m+1] = -expf(v.y) * 1.4426950408889634f;
            A[4*m+2] = -expf(v.z) * 1.4426950408889634f;
            A[4*m+3] = -expf(v.w) * 1.4426950408889634f;
        }
    }

    float h[16];
    {
        const float4* hin = (const float4*)(g_hend + (((size_t)bk*NC + c)*Dn + d)*16);
        #pragma unroll
        for (int m = 0; m < 4; m++) {
            float4 v = hin[m];
            h[4*m+0] = v.x; h[4*m+1] = v.y; h[4*m+2] = v.z; h[4*m+3] = v.w;
        }
    }
    const float Dd = Ds[k*Dn + d];

    const float2* du = ((const float2*)g_DU) + ((size_t)bk*Ln + (size_t)c*Lc)*Dn + d;
    float* ymb = g_ym + (size_t)b*Ln*Dn + d;

    float2 ring[4];
    #pragma unroll
    for (int i = 0; i < 4; i++) ring[i] = du[(size_t)i*Dn];
    du += 4*Dn;

    float dA[16];
    #pragma unroll
    for (int n = 0; n < 16; n++) dA[n] = ex2f(ring[0].x * A[n]);

    #pragma unroll 4
    for (int t = 0; t < Lc; t++) {
        float2 cur = ring[t & 3];
        ring[t & 3] = du[0]; du += Dn;
        float dt = cur.x, u = cur.y, dtu = dt*u;
        float pa = 0.f, pb = 0.f;
        #pragma unroll
        for (int m = 0; m < 4; m++) {
            float4 q = sB[t*4 + m];
            float4 r = sC[t*4 + m];
            h[4*m+0] = fmaf(dA[4*m+0], h[4*m+0], dtu*q.x);
            h[4*m+1] = fmaf(dA[4*m+1], h[4*m+1], dtu*q.y);
            h[4*m+2] = fmaf(dA[4*m+2], h[4*m+2], dtu*q.z);
            h[4*m+3] = fmaf(dA[4*m+3], h[4*m+3], dtu*q.w);
            pa = fmaf(h[4*m+0], r.x, pa);
            pb = fmaf(h[4*m+1], r.y, pb);
            pa = fmaf(h[4*m+2], r.z, pa);
            pb = fmaf(h[4*m+3], r.w, pb);
        }
        float yv = fmaf(Dd, u, pa + pb);

        // canonical merged position pm for this direction's sequence index l
        int l = c*Lc + t;
        int pm;
        if (k == 0)      pm = l;
        else if (k == 1) pm = ((l & 63) << 6) | (l >> 6);
        else if (k == 2) pm = 4095 - l;
        else { int lr = 4095 - l; pm = ((lr & 63) << 6) | (lr >> 6); }

        float* yp = ymb + (size_t)pm*Dn;
        if (k == 0) *yp = yv;
        else        *yp = *yp + yv;

        float dtn = ring[(t+1) & 3].x;
        #pragma unroll
        for (int n = 0; n < 16; n++) dA[n] = ex2f(dtn * A[n]);
    }
}

// ---------------------------------------------------------------------------
// LayerNorm over channel dim on the pre-merged y.
// ---------------------------------------------------------------------------
__global__ __launch_bounds__(256) void ln_kernel(
    const float* __restrict__ gamma, const float* __restrict__ beta,
    float* __restrict__ out)
{
    const int bid  = blockIdx.x;
    const int b    = bid >> 9;
    const int l    = ((bid & 511) << 3) + (threadIdx.x >> 5);
    const int lane = threadIdx.x & 31;

    const float* ym = g_ym + ((size_t)b*Ln + l)*Dn;

    float v[6]; float s = 0.f;
    #pragma unroll
    for (int i = 0; i < 6; i++) {
        v[i] = ym[lane + 32*i];
        s += v[i];
    }
    #pragma unroll
    for (int o = 16; o; o >>= 1) s += __shfl_xor_sync(0xffffffffu, s, o);
    float mean = s * (1.f/192.f);
    float var = 0.f;
    #pragma unroll
    for (int i = 0; i < 6; i++) { float z = v[i] - mean; var = fmaf(z, z, var); }
    #pragma unroll
    for (int o = 16; o; o >>= 1) var += __shfl_xor_sync(0xffffffffu, var, o);
    float rstd = rsqrtf(var*(1.f/192.f) + 1e-5f);

    size_t ob = ((size_t)b*Ln + l)*Dn;
    #pragma unroll
    for (int i = 0; i < 6; i++) {
        int dd = lane + 32*i;
        out[ob + dd] = fmaf((v[i] - mean)*rstd, gamma[dd], beta[dd]);
    }
}

extern "C" void kernel_launch(void* const* d_in, const int* in_sizes, int n_in,
                              void* d_out, int out_size) {
    const float* x    = (const float*)d_in[0];
    const float* xpw  = (const float*)d_in[1];
    const float* dtw  = (const float*)d_in[2];
    const float* dtb  = (const float*)d_in[3];
    const float* Alog = (const float*)d_in[4];
    const float* Ds   = (const float*)d_in[5];
    const float* gam  = (const float*)d_in[6];
    const float* bet  = (const float*)d_in[7];
    float* out = (float*)d_out;

    proj_kernel<<<Bn*Kn*64, 256>>>(x, xpw, dtw, dtb);
    scan_p1<<<32*NC, 192>>>(Alog);
    scan_mid<<<(32*Dn*Nn + 255)/256, 256>>>(Alog);
    scan_p2<<<Bn*NC, 192>>>(Alog, Ds, 0);
    scan_p2<<<Bn*NC, 192>>>(Alog, Ds, 1);
    scan_p2<<<Bn*NC, 192>>>(Alog, Ds, 2);
    scan_p2<<<Bn*NC, 192>>>(Alog, Ds, 3);
    ln_kernel<<<Bn*512, 256>>>(gam, bet, out);
}

// round 12
// speedup vs baseline: 1.5298x; 1.5298x over previous
#include <cuda_runtime.h>

#define Bn 8
#define Dn 192
#define Ln 4096
#define Nn 16
#define Rn 6
#define Cn 38
#define Kn 4
#define NC 32
#define Lc 128
#define XP 65   // padded row length for xt (conflict-free d-fast reads)

// scratch (allocation-free device globals); DU padded 4 steps for prefetch ring
__device__ float g_DU[(size_t)Bn*Kn*Ln*Dn*2 + Dn*8];
__device__ float g_B [(size_t)Bn*Kn*Ln*Nn];
__device__ float g_C [(size_t)Bn*Kn*Ln*Nn];
__device__ float g_ys[(size_t)Bn*Kn*Ln*Dn];
__device__ float g_hend[(size_t)Bn*Kn*NC*Dn*Nn];
__device__ float g_S[(size_t)Bn*Kn*NC*Dn];

__device__ __forceinline__ float ex2f(float x){
    float r; asm("ex2.approx.ftz.f32 %0, %1;" : "=f"(r) : "f"(x)); return r;
}
__device__ __forceinline__ float lg2f(float x){
    float r; asm("lg2.approx.ftz.f32 %0, %1;" : "=f"(r) : "f"(x)); return r;
}

// ---------------------------------------------------------------------------
// Kernel A: cross-scan gather + x_proj + dt_proj + softplus.
// R8 structure; xt rows padded to 65 floats -> conflict-free u reads in stage 3.
// ---------------------------------------------------------------------------
__global__ __launch_bounds__(256, 3) void proj_kernel(
    const float* __restrict__ x, const float* __restrict__ xpw,
    const float* __restrict__ dtw, const float* __restrict__ dtb)
{
    __shared__ float xt[Dn*XP];        // xt[d][j], padded
    __shared__ float dts_s[Rn][64];
    __shared__ float sB[64][16];
    __shared__ float sC[64][16];

    const int bid = blockIdx.x;        // 2048 = 8*4*64
    const int t   = bid & 63;
    const int k   = (bid >> 6) & 3;
    const int b   = bid >> 8;
    const int tid = threadIdx.x;

    int p0, pstep;
    if (k == 2) { p0 = 4095 - t*64; pstep = -1; }
    else        { p0 = t*64;        pstep = 1;  }

    const float* xb = x + (size_t)b*Dn*Ln;
    for (int idx = tid; idx < Dn*64; idx += 256) {
        int d = idx >> 6, j = idx & 63;
        xt[d*XP + j] = xb[(size_t)d*Ln + p0 + j*pstep];
    }
    __syncthreads();

    auto lof = [&](int j) -> int {
        if (k == 1) return j*64 + t;
        if (k == 3) return 4095 - j*64 - t;
        return t*64 + j;
    };

    {
        const int j = tid & 31;        // positions j and j+32
        const int w = tid >> 5;

        float acc[5][2];
        #pragma unroll
        for (int m = 0; m < 5; m++) { acc[m][0] = 0.f; acc[m][1] = 0.f; }
        const float4* wp[5];
        #pragma unroll
        for (int m = 0; m < 5; m++) {
            int c = w + 8*m; if (c > Cn-1) c = Cn-1;
            wp[m] = (const float4*)(xpw + (size_t)(k*Cn + c)*Dn);
        }
        #pragma unroll 2
        for (int i = 0; i < Dn/4; i++) {
            float a0 = xt[(4*i+0)*XP + j],  b0 = xt[(4*i+0)*XP + j+32];
            float a1 = xt[(4*i+1)*XP + j],  b1 = xt[(4*i+1)*XP + j+32];
            float a2 = xt[(4*i+2)*XP + j],  b2 = xt[(4*i+2)*XP + j+32];
            float a3 = xt[(4*i+3)*XP + j],  b3 = xt[(4*i+3)*XP + j+32];
            #pragma unroll
            for (int m = 0; m < 5; m++) {
                float4 wv = wp[m][i];
                acc[m][0] = fmaf(wv.x, a0, acc[m][0]);
                acc[m][1] = fmaf(wv.x, b0, acc[m][1]);
                acc[m][0] = fmaf(wv.y, a1, acc[m][0]);
                acc[m][1] = fmaf(wv.y, b1, acc[m][1]);
                acc[m][0] = fmaf(wv.z, a2, acc[m][0]);
                acc[m][1] = fmaf(wv.z, b2, acc[m][1]);
                acc[m][0] = fmaf(wv.w, a3, acc[m][0]);
                acc[m][1] = fmaf(wv.w, b3, acc[m][1]);
            }
        }
        #pragma unroll
        for (int m = 0; m < 5; m++) {
            int c = w + 8*m;
            if (c < Rn) { dts_s[c][j] = acc[m][0]; dts_s[c][j+32] = acc[m][1]; }
            else if (c < Cn) {
                int n = c - Rn;
                if (n < Nn) { sB[j][n] = acc[m][0]; sB[j+32][n] = acc[m][1]; }
                else        { int nn = n - Nn;
                              sC[j][nn] = acc[m][0]; sC[j+32][nn] = acc[m][1]; }
            }
        }
    }
    __syncthreads();

    {
        const int pos = tid >> 2, nq = tid & 3;
        const size_t base = ((size_t)(b*Kn + k)*Ln + lof(pos))*(size_t)Nn + 4*nq;
        *(float4*)&g_B[base] = *(const float4*)&sB[pos][4*nq];
        *(float4*)&g_C[base] = *(const float4*)&sC[pos][4*nq];
    }

    // delta = softplus(dt_w @ dts + bias); store (delta,u) interleaved
    for (int idx = tid; idx < Dn*64; idx += 256) {
        int d = idx % Dn, j = idx / Dn;
        float acc = dtb[k*Dn + d];
        #pragma unroll
        for (int r = 0; r < Rn; r++) acc = fmaf(dts_s[r][j], dtw[(k*Dn + d)*Rn + r], acc);
        float e = ex2f(acc * 1.4426950408889634f);
        float sp = 0.6931471805599453f * lg2f(1.f + e);
        if (acc > 20.f) sp = acc;
        float u = xt[d*XP + j];                 // conflict-free (padded)
        int l = lof(j);
        size_t o = ((size_t)(b*Kn + k)*Ln + l)*Dn + d;
        ((float2*)g_DU)[o] = make_float2(sp, u);
    }
}

// ---------------------------------------------------------------------------
// Scan pass 1: lane=channel, A/h/dA in regs, ring-4 DU prefetch, hoisted EX2.
// ---------------------------------------------------------------------------
__global__ __launch_bounds__(192, 4) void scan_p1(const float* __restrict__ A_logs)
{
    __shared__ float4 sB[Lc*4];
    const int bk = blockIdx.x >> 5;
    const int c  = blockIdx.x & 31;
    const int d  = threadIdx.x;
    const int k  = bk & 3;

    const float4* gb = (const float4*)(g_B + ((size_t)bk*Ln + (size_t)c*Lc)*16);
    for (int i = d; i < Lc*4; i += 192) sB[i] = gb[i];
    __syncthreads();

    float A[16];
    {
        const float4* al = (const float4*)(A_logs + (size_t)(k*Dn + d)*16);
        #pragma unroll
        for (int m = 0; m < 4; m++) {
            float4 v = al[m];
            A[4*m+0] = -expf(v.x) * 1.4426950408889634f;
            A[4*m+1] = -expf(v.y) * 1.4426950408889634f;
            A[4*m+2] = -expf(v.z) * 1.4426950408889634f;
            A[4*m+3] = -expf(v.w) * 1.4426950408889634f;
        }
    }

    float h[16];
    #pragma unroll
    for (int n = 0; n < 16; n++) h[n] = 0.f;
    float S = 0.f;

    const float2* du = ((const float2*)g_DU) + ((size_t)bk*Ln + (size_t)c*Lc)*Dn + d;
    float2 ring[4];
    #pragma unroll
    for (int i = 0; i < 4; i++) ring[i] = du[(size_t)i*Dn];
    du += 4*Dn;

    float dA[16];
    #pragma unroll
    for (int n = 0; n < 16; n++) dA[n] = ex2f(ring[0].x * A[n]);

    #pragma unroll 4
    for (int t = 0; t < Lc; t++) {
        float2 cur = ring[t & 3];
        ring[t & 3] = du[0]; du += Dn;
        float dt = cur.x, dtu = dt*cur.y;
        S += dt;
        #pragma unroll
        for (int m = 0; m < 4; m++) {
            float4 q = sB[t*4 + m];
            h[4*m+0] = fmaf(dA[4*m+0], h[4*m+0], dtu*q.x);
            h[4*m+1] = fmaf(dA[4*m+1], h[4*m+1], dtu*q.y);
            h[4*m+2] = fmaf(dA[4*m+2], h[4*m+2], dtu*q.z);
            h[4*m+3] = fmaf(dA[4*m+3], h[4*m+3], dtu*q.w);
        }
        float dtn = ring[(t+1) & 3].x;
        #pragma unroll
        for (int n = 0; n < 16; n++) dA[n] = ex2f(dtn * A[n]);
    }

    float4* out = (float4*)(g_hend + (((size_t)bk*NC + c)*Dn + d)*16);
    #pragma unroll
    for (int m = 0; m < 4; m++) out[m] = make_float4(h[4*m], h[4*m+1], h[4*m+2], h[4*m+3]);
    g_S[((size_t)bk*NC + c)*Dn + d] = S;
}

// ---------------------------------------------------------------------------
// Scan mid: chain chunk summaries -> exclusive h_init prefix (in place).
// ---------------------------------------------------------------------------
__global__ __launch_bounds__(256) void scan_mid(const float* __restrict__ A_logs)
{
    int gid = blockIdx.x*256 + threadIdx.x;
    if (gid >= 32*Dn*Nn) return;
    int n  = gid & 15;
    int d  = (gid >> 4) % Dn;
    int bk = gid / (Dn*16);
    int k  = bk & 3;
    float A = -expf(A_logs[(size_t)(k*Dn + d)*16 + n]) * 1.4426950408889634f;
    float h = 0.f;
    for (int c = 0; c < NC; c++) {
        size_t o = (((size_t)bk*NC + c)*Dn + d)*16 + n;
        float hend = g_hend[o];
        float S = g_S[((size_t)bk*NC + c)*Dn + d];
        g_hend[o] = h;
        h = fmaf(ex2f(A*S), h, hend);
    }
}

// ---------------------------------------------------------------------------
// Scan pass 2: rescan from h_init, emit y (bk,l,d). Stages B and C.
// ---------------------------------------------------------------------------
__global__ __launch_bounds__(192, 4) void scan_p2(
    const float* __restrict__ A_logs, const float* __restrict__ Ds)
{
    __shared__ float4 sB[Lc*4];
    __shared__ float4 sC[Lc*4];
    const int bk = blockIdx.x >> 5;
    const int c  = blockIdx.x & 31;
    const int d  = threadIdx.x;
    const int k  = bk & 3;

    const float4* gb = (const float4*)(g_B + ((size_t)bk*Ln + (size_t)c*Lc)*16);
    const float4* gc = (const float4*)(g_C + ((size_t)bk*Ln + (size_t)c*Lc)*16);
    for (int i = d; i < Lc*4; i += 192) { sB[i] = gb[i]; sC[i] = gc[i]; }
    __syncthreads();

    float A[16];
    {
        const float4* al = (const float4*)(A_logs + (size_t)(k*Dn + d)*16);
        #pragma unroll
        for (int m = 0; m < 4; m++) {
            float4 v = al[m];
            A[4*m+0] = -expf(v.x) * 1.4426950408889634f;
            A[4*m+1] = -expf(v.y) * 1.4426950408889634f;
            A[4*m+2] = -expf(v.z) * 1.4426950408889634f;
            A[4*m+3] = -expf(v.w) * 1.4426950408889634f;
        }
    }

    float h[16];
    {
        const float4* hin = (const float4*)(g_hend + (((size_t)bk*NC + c)*Dn + d)*16);
        #pragma unroll
        for (int m = 0; m < 4; m++) {
            float4 v = hin[m];
            h[4*m+0] = v.x; h[4*m+1] = v.y; h[4*m+2] = v.z; h[4*m+3] = v.w;
        }
    }
    const float Dd = Ds[k*Dn + d];

    const float2* du = ((const float2*)g_DU) + ((size_t)bk*Ln + (size_t)c*Lc)*Dn + d;
    float* yo = g_ys + ((size_t)bk*Ln + (size_t)c*Lc)*Dn + d;

    float2 ring[4];
    #pragma unroll
    for (int i = 0; i < 4; i++) ring[i] = du[(size_t)i*Dn];
    du += 4*Dn;

    float dA[16];
    #pragma unroll
    for (int n = 0; n < 16; n++) dA[n] = ex2f(ring[0].x * A[n]);

    #pragma unroll 4
    for (int t = 0; t < Lc; t++) {
        float2 cur = ring[t & 3];
        ring[t & 3] = du[0]; du += Dn;
        float dt = cur.x, u = cur.y, dtu = dt*u;
        float pa = 0.f, pb = 0.f;
        #pragma unroll
        for (int m = 0; m < 4; m++) {
            float4 q = sB[t*4 + m];
            float4 r = sC[t*4 + m];
            h[4*m+0] = fmaf(dA[4*m+0], h[4*m+0], dtu*q.x);
            h[4*m+1] = fmaf(dA[4*m+1], h[4*m+1], dtu*q.y);
            h[4*m+2] = fmaf(dA[4*m+2], h[4*m+2], dtu*q.z);
            h[4*m+3] = fmaf(dA[4*m+3], h[4*m+3], dtu*q.w);
            pa = fmaf(h[4*m+0], r.x, pa);
            pb = fmaf(h[4*m+1], r.y, pb);
            pa = fmaf(h[4*m+2], r.z, pa);
            pb = fmaf(h[4*m+3], r.w, pb);
        }
        yo[(size_t)t*Dn] = fmaf(Dd, u, pa + pb);
        float dtn = ring[(t+1) & 3].x;
        #pragma unroll
        for (int n = 0; n < 16; n++) dA[n] = ex2f(dtn * A[n]);
    }
}

// ---------------------------------------------------------------------------
// CrossMerge + LayerNorm.
// ---------------------------------------------------------------------------
__global__ __launch_bounds__(256) void merge_ln_kernel(
    const float* __restrict__ gamma, const float* __restrict__ beta,
    float* __restrict__ out)
{
    const int bid  = blockIdx.x;
    const int b    = bid >> 9;
    const int l    = ((bid & 511) << 3) + (threadIdx.x >> 5);
    const int lane = threadIdx.x & 31;
    const int hh = l >> 6, ww = l & 63;
    const int lT = ww*64 + hh;

    const float* y0 = g_ys + ((size_t)(b*4+0)*Ln + l)*Dn;
    const float* y1 = g_ys + ((size_t)(b*4+1)*Ln + lT)*Dn;
    const float* y2 = g_ys + ((size_t)(b*4+2)*Ln + (4095 - l))*Dn;
    const float* y3 = g_ys + ((size_t)(b*4+3)*Ln + (4095 - lT))*Dn;

    float v[6]; float s = 0.f;
    #pragma unroll
    for (int i = 0; i < 6; i++) {
        int dd = lane + 32*i;
        v[i] = y0[dd] + y1[dd] + y2[dd] + y3[dd];
        s += v[i];
    }
    #pragma unroll
    for (int o = 16; o; o >>= 1) s += __shfl_xor_sync(0xffffffffu, s, o);
    float mean = s * (1.f/192.f);
    float var = 0.f;
    #pragma unroll
    for (int i = 0; i < 6; i++) { float z = v[i] - mean; var = fmaf(z, z, var); }
    #pragma unroll
    for (int o = 16; o; o >>= 1) var += __shfl_xor_sync(0xffffffffu, var, o);
    float rstd = rsqrtf(var*(1.f/192.f) + 1e-5f);

    size_t ob = ((size_t)b*Ln + l)*Dn;
    #pragma unroll
    for (int i = 0; i < 6; i++) {
        int dd = lane + 32*i;
        out[ob + dd] = fmaf((v[i] - mean)*rstd, gamma[dd], beta[dd]);
    }
}

extern "C" void kernel_launch(void* const* d_in, const int* in_sizes, int n_in,
                              void* d_out, int out_size) {
    const float* x    = (const float*)d_in[0];
    const float* xpw  = (const float*)d_in[1];
    const float* dtw  = (const float*)d_in[2];
    const float* dtb  = (const float*)d_in[3];
    const float* Alog = (const float*)d_in[4];
    const float* Ds   = (const float*)d_in[5];
    const float* gam  = (const float*)d_in[6];
    const float* bet  = (const float*)d_in[7];
    float* out = (float*)d_out;

    proj_kernel<<<Bn*Kn*64, 256>>>(x, xpw, dtw, dtb);
    scan_p1<<<32*NC, 192>>>(Alog);
    scan_mid<<<(32*Dn*Nn + 255)/256, 256>>>(Alog);
    scan_p2<<<32*NC, 192>>>(Alog, Ds);
    merge_ln_kernel<<<Bn*512, 256>>>(gam, bet, out);
}

// round 13
// speedup vs baseline: 1.7122x; 1.1192x over previous
#include <cuda_runtime.h>

#define Bn 8
#define Dn 192
#define Ln 4096
#define Nn 16
#define Rn 6
#define Cn 38
#define Kn 4
#define NC 32
#define Lc 128
#define XP 65   // padded row length for xt (conflict-free d-fast reads)

// scratch (allocation-free device globals); DU padded 4 steps for prefetch ring
__device__ float g_DU[(size_t)Bn*Kn*Ln*Dn*2 + Dn*8];
__device__ float g_B [(size_t)Bn*Kn*Ln*Nn];
__device__ float g_C [(size_t)Bn*Kn*Ln*Nn];
__device__ float g_ys[(size_t)Bn*Kn*Ln*Dn];
__device__ float g_hend[(size_t)Bn*Kn*NC*Dn*Nn];
__device__ float g_S[(size_t)Bn*Kn*NC*Dn];

__device__ __forceinline__ float ex2f(float x){
    float r; asm("ex2.approx.ftz.f32 %0, %1;" : "=f"(r) : "f"(x)); return r;
}
__device__ __forceinline__ float lg2f(float x){
    float r; asm("lg2.approx.ftz.f32 %0, %1;" : "=f"(r) : "f"(x)); return r;
}

// ---------------------------------------------------------------------------
// Kernel A: cross-scan gather + x_proj + dt_proj + softplus.
// xt padded (R12); sB/sC transposed [16][65] -> conflict-free scatter stores;
// stage 3: thread-owns-channel with hoisted dt weights (no LDG in loop).
// ---------------------------------------------------------------------------
__global__ __launch_bounds__(256, 3) void proj_kernel(
    const float* __restrict__ x, const float* __restrict__ xpw,
    const float* __restrict__ dtw, const float* __restrict__ dtb)
{
    __shared__ float xt[Dn*XP];        // xt[d][j], padded
    __shared__ float dts_s[Rn][64];
    __shared__ float sB[16][65];       // [n][j], padded
    __shared__ float sC[16][65];

    const int bid = blockIdx.x;        // 2048 = 8*4*64
    const int t   = bid & 63;
    const int k   = (bid >> 6) & 3;
    const int b   = bid >> 8;
    const int tid = threadIdx.x;

    int p0, pstep;
    if (k == 2) { p0 = 4095 - t*64; pstep = -1; }
    else        { p0 = t*64;        pstep = 1;  }

    const float* xb = x + (size_t)b*Dn*Ln;
    for (int idx = tid; idx < Dn*64; idx += 256) {
        int d = idx >> 6, j = idx & 63;
        xt[d*XP + j] = xb[(size_t)d*Ln + p0 + j*pstep];
    }
    __syncthreads();

    auto lof = [&](int j) -> int {
        if (k == 1) return j*64 + t;
        if (k == 3) return 4095 - j*64 - t;
        return t*64 + j;
    };

    {
        const int j = tid & 31;        // positions j and j+32
        const int w = tid >> 5;

        float acc[5][2];
        #pragma unroll
        for (int m = 0; m < 5; m++) { acc[m][0] = 0.f; acc[m][1] = 0.f; }
        const float4* wp[5];
        #pragma unroll
        for (int m = 0; m < 5; m++) {
            int c = w + 8*m; if (c > Cn-1) c = Cn-1;
            wp[m] = (const float4*)(xpw + (size_t)(k*Cn + c)*Dn);
        }
        #pragma unroll 2
        for (int i = 0; i < Dn/4; i++) {
            float a0 = xt[(4*i+0)*XP + j],  b0 = xt[(4*i+0)*XP + j+32];
            float a1 = xt[(4*i+1)*XP + j],  b1 = xt[(4*i+1)*XP + j+32];
            float a2 = xt[(4*i+2)*XP + j],  b2 = xt[(4*i+2)*XP + j+32];
            float a3 = xt[(4*i+3)*XP + j],  b3 = xt[(4*i+3)*XP + j+32];
            #pragma unroll
            for (int m = 0; m < 5; m++) {
                float4 wv = wp[m][i];
                acc[m][0] = fmaf(wv.x, a0, acc[m][0]);
                acc[m][1] = fmaf(wv.x, b0, acc[m][1]);
                acc[m][0] = fmaf(wv.y, a1, acc[m][0]);
                acc[m][1] = fmaf(wv.y, b1, acc[m][1]);
                acc[m][0] = fmaf(wv.z, a2, acc[m][0]);
                acc[m][1] = fmaf(wv.z, b2, acc[m][1]);
                acc[m][0] = fmaf(wv.w, a3, acc[m][0]);
                acc[m][1] = fmaf(wv.w, b3, acc[m][1]);
            }
        }
        #pragma unroll
        for (int m = 0; m < 5; m++) {
            int c = w + 8*m;
            if (c < Rn) { dts_s[c][j] = acc[m][0]; dts_s[c][j+32] = acc[m][1]; }
            else if (c < Cn) {
                int n = c - Rn;
                if (n < Nn) { sB[n][j] = acc[m][0]; sB[n][j+32] = acc[m][1]; }
                else        { int nn = n - Nn;
                              sC[nn][j] = acc[m][0]; sC[nn][j+32] = acc[m][1]; }
            }
        }
    }
    __syncthreads();

    // coalesced B/C output: assemble float4 from transposed smem
    {
        const int pos = tid >> 2, nq = tid & 3;
        float4 vB, vC;
        vB.x = sB[4*nq+0][pos]; vB.y = sB[4*nq+1][pos];
        vB.z = sB[4*nq+2][pos]; vB.w = sB[4*nq+3][pos];
        vC.x = sC[4*nq+0][pos]; vC.y = sC[4*nq+1][pos];
        vC.z = sC[4*nq+2][pos]; vC.w = sC[4*nq+3][pos];
        const size_t base = ((size_t)(b*Kn + k)*Ln + lof(pos))*(size_t)Nn + 4*nq;
        *(float4*)&g_B[base] = vB;
        *(float4*)&g_C[base] = vC;
    }

    // stage 3: delta = softplus(dt_w @ dts + bias); thread owns channel d.
    if (tid < Dn) {
        const int d = tid;
        float wr[6];
        #pragma unroll
        for (int r = 0; r < Rn; r++) wr[r] = dtw[(k*Dn + d)*Rn + r];
        const float bias = dtb[k*Dn + d];
        const float* xrow = xt + d*XP;
        float2* dub = ((float2*)g_DU) + (size_t)(b*Kn + k)*Ln*Dn + d;
        #pragma unroll 4
        for (int j = 0; j < 64; j++) {
            float acc = bias;
            #pragma unroll
            for (int r = 0; r < Rn; r++) acc = fmaf(dts_s[r][j], wr[r], acc);
            float e = ex2f(acc * 1.4426950408889634f);
            float sp = 0.6931471805599453f * lg2f(1.f + e);
            if (acc > 20.f) sp = acc;
            dub[(size_t)lof(j)*Dn] = make_float2(sp, xrow[j]);
        }
    }
}

// ---------------------------------------------------------------------------
// Scan pass 1: lane=channel, A/h/dA in regs, ring-4 DU prefetch, hoisted EX2.
// ---------------------------------------------------------------------------
__global__ __launch_bounds__(192, 4) void scan_p1(const float* __restrict__ A_logs)
{
    __shared__ float4 sB[Lc*4];
    const int bk = blockIdx.x >> 5;
    const int c  = blockIdx.x & 31;
    const int d  = threadIdx.x;
    const int k  = bk & 3;

    const float4* gb = (const float4*)(g_B + ((size_t)bk*Ln + (size_t)c*Lc)*16);
    for (int i = d; i < Lc*4; i += 192) sB[i] = gb[i];
    __syncthreads();

    float A[16];
    {
        const float4* al = (const float4*)(A_logs + (size_t)(k*Dn + d)*16);
        #pragma unroll
        for (int m = 0; m < 4; m++) {
            float4 v = al[m];
            A[4*m+0] = -expf(v.x) * 1.4426950408889634f;
            A[4*m+1] = -expf(v.y) * 1.4426950408889634f;
            A[4*m+2] = -expf(v.z) * 1.4426950408889634f;
            A[4*m+3] = -expf(v.w) * 1.4426950408889634f;
        }
    }

    float h[16];
    #pragma unroll
    for (int n = 0; n < 16; n++) h[n] = 0.f;
    float S = 0.f;

    const float2* du = ((const float2*)g_DU) + ((size_t)bk*Ln + (size_t)c*Lc)*Dn + d;
    float2 ring[4];
    #pragma unroll
    for (int i = 0; i < 4; i++) ring[i] = du[(size_t)i*Dn];
    du += 4*Dn;

    float dA[16];
    #pragma unroll
    for (int n = 0; n < 16; n++) dA[n] = ex2f(ring[0].x * A[n]);

    #pragma unroll 4
    for (int t = 0; t < Lc; t++) {
        float2 cur = ring[t & 3];
        ring[t & 3] = du[0]; du += Dn;
        float dt = cur.x, dtu = dt*cur.y;
        S += dt;
        #pragma unroll
        for (int m = 0; m < 4; m++) {
            float4 q = sB[t*4 + m];
            h[4*m+0] = fmaf(dA[4*m+0], h[4*m+0], dtu*q.x);
            h[4*m+1] = fmaf(dA[4*m+1], h[4*m+1], dtu*q.y);
            h[4*m+2] = fmaf(dA[4*m+2], h[4*m+2], dtu*q.z);
            h[4*m+3] = fmaf(dA[4*m+3], h[4*m+3], dtu*q.w);
        }
        float dtn = ring[(t+1) & 3].x;
        #pragma unroll
        for (int n = 0; n < 16; n++) dA[n] = ex2f(dtn * A[n]);
    }

    float4* out = (float4*)(g_hend + (((size_t)bk*NC + c)*Dn + d)*16);
    #pragma unroll
    for (int m = 0; m < 4; m++) out[m] = make_float4(h[4*m], h[4*m+1], h[4*m+2], h[4*m+3]);
    g_S[((size_t)bk*NC + c)*Dn + d] = S;
}

// ---------------------------------------------------------------------------
// Scan mid: chain chunk summaries -> exclusive h_init prefix (in place).
// ---------------------------------------------------------------------------
__global__ __launch_bounds__(256) void scan_mid(const float* __restrict__ A_logs)
{
    int gid = blockIdx.x*256 + threadIdx.x;
    if (gid >= 32*Dn*Nn) return;
    int n  = gid & 15;
    int d  = (gid >> 4) % Dn;
    int bk = gid / (Dn*16);
    int k  = bk & 3;
    float A = -expf(A_logs[(size_t)(k*Dn + d)*16 + n]) * 1.4426950408889634f;
    float h = 0.f;
    for (int c = 0; c < NC; c++) {
        size_t o = (((size_t)bk*NC + c)*Dn + d)*16 + n;
        float hend = g_hend[o];
        float S = g_S[((size_t)bk*NC + c)*Dn + d];
        g_hend[o] = h;
        h = fmaf(ex2f(A*S), h, hend);
    }
}

// ---------------------------------------------------------------------------
// Scan pass 2: rescan from h_init, emit y (bk,l,d). Stages B and C.
// ---------------------------------------------------------------------------
__global__ __launch_bounds__(192, 4) void scan_p2(
    const float* __restrict__ A_logs, const float* __restrict__ Ds)
{
    __shared__ float4 sB[Lc*4];
    __shared__ float4 sC[Lc*4];
    const int bk = blockIdx.x >> 5;
    const int c  = blockIdx.x & 31;
    const int d  = threadIdx.x;
    const int k  = bk & 3;

    const float4* gb = (const float4*)(g_B + ((size_t)bk*Ln + (size_t)c*Lc)*16);
    const float4* gc = (const float4*)(g_C + ((size_t)bk*Ln + (size_t)c*Lc)*16);
    for (int i = d; i < Lc*4; i += 192) { sB[i] = gb[i]; sC[i] = gc[i]; }
    __syncthreads();

    float A[16];
    {
        const float4* al = (const float4*)(A_logs + (size_t)(k*Dn + d)*16);
        #pragma unroll
        for (int m = 0; m < 4; m++) {
            float4 v = al[m];
            A[4*m+0] = -expf(v.x) * 1.4426950408889634f;
            A[4*m+1] = -expf(v.y) * 1.4426950408889634f;
            A[4*m+2] = -expf(v.z) * 1.4426950408889634f;
            A[4*m+3] = -expf(v.w) * 1.4426950408889634f;
        }
    }

    float h[16];
    {
        const float4* hin = (const float4*)(g_hend + (((size_t)bk*NC + c)*Dn + d)*16);
        #pragma unroll
        for (int m = 0; m < 4; m++) {
            float4 v = hin[m];
            h[4*m+0] = v.x; h[4*m+1] = v.y; h[4*m+2] = v.z; h[4*m+3] = v.w;
        }
    }
    const float Dd = Ds[k*Dn + d];

    const float2* du = ((const float2*)g_DU) + ((size_t)bk*Ln + (size_t)c*Lc)*Dn + d;
    float* yo = g_ys + ((size_t)bk*Ln + (size_t)c*Lc)*Dn + d;

    float2 ring[4];
    #pragma unroll
    for (int i = 0; i < 4; i++) ring[i] = du[(size_t)i*Dn];
    du += 4*Dn;

    float dA[16];
    #pragma unroll
    for (int n = 0; n < 16; n++) dA[n] = ex2f(ring[0].x * A[n]);

    #pragma unroll 4
    for (int t = 0; t < Lc; t++) {
        float2 cur = ring[t & 3];
        ring[t & 3] = du[0]; du += Dn;
        float dt = cur.x, u = cur.y, dtu = dt*u;
        float pa = 0.f, pb = 0.f;
        #pragma unroll
        for (int m = 0; m < 4; m++) {
            float4 q = sB[t*4 + m];
            float4 r = sC[t*4 + m];
            h[4*m+0] = fmaf(dA[4*m+0], h[4*m+0], dtu*q.x);
            h[4*m+1] = fmaf(dA[4*m+1], h[4*m+1], dtu*q.y);
            h[4*m+2] = fmaf(dA[4*m+2], h[4*m+2], dtu*q.z);
            h[4*m+3] = fmaf(dA[4*m+3], h[4*m+3], dtu*q.w);
            pa = fmaf(h[4*m+0], r.x, pa);
            pb = fmaf(h[4*m+1], r.y, pb);
            pa = fmaf(h[4*m+2], r.z, pa);
            pb = fmaf(h[4*m+3], r.w, pb);
        }
        yo[(size_t)t*Dn] = fmaf(Dd, u, pa + pb);
        float dtn = ring[(t+1) & 3].x;
        #pragma unroll
        for (int n = 0; n < 16; n++) dA[n] = ex2f(dtn * A[n]);
    }
}

// ---------------------------------------------------------------------------
// CrossMerge + LayerNorm.
// ---------------------------------------------------------------------------
__global__ __launch_bounds__(256) void merge_ln_kernel(
    const float* __restrict__ gamma, const float* __restrict__ beta,
    float* __restrict__ out)
{
    const int bid  = blockIdx.x;
    const int b    = bid >> 9;
    const int l    = ((bid & 511) << 3) + (threadIdx.x >> 5);
    const int lane = threadIdx.x & 31;
    const int hh = l >> 6, ww = l & 63;
    const int lT = ww*64 + hh;

    const float* y0 = g_ys + ((size_t)(b*4+0)*Ln + l)*Dn;
    const float* y1 = g_ys + ((size_t)(b*4+1)*Ln + lT)*Dn;
    const float* y2 = g_ys + ((size_t)(b*4+2)*Ln + (4095 - l))*Dn;
    const float* y3 = g_ys + ((size_t)(b*4+3)*Ln + (4095 - lT))*Dn;

    float v[6]; float s = 0.f;
    #pragma unroll
    for (int i = 0; i < 6; i++) {
        int dd = lane + 32*i;
        v[i] = y0[dd] + y1[dd] + y2[dd] + y3[dd];
        s += v[i];
    }
    #pragma unroll
    for (int o = 16; o; o >>= 1) s += __shfl_xor_sync(0xffffffffu, s, o);
    float mean = s * (1.f/192.f);
    float var = 0.f;
    #pragma unroll
    for (int i = 0; i < 6; i++) { float z = v[i] - mean; var = fmaf(z, z, var); }
    #pragma unroll
    for (int o = 16; o; o >>= 1) var += __shfl_xor_sync(0xffffffffu, var, o);
    float rstd = rsqrtf(var*(1.f/192.f) + 1e-5f);

    size_t ob = ((size_t)b*Ln + l)*Dn;
    #pragma unroll
    for (int i = 0; i < 6; i++) {
        int dd = lane + 32*i;
        out[ob + dd] = fmaf((v[i] - mean)*rstd, gamma[dd], beta[dd]);
    }
}

extern "C" void kernel_launch(void* const* d_in, const int* in_sizes, int n_in,
                              void* d_out, int out_size) {
    const float* x    = (const float*)d_in[0];
    const float* xpw  = (const float*)d_in[1];
    const float* dtw  = (const float*)d_in[2];
    const float* dtb  = (const float*)d_in[3];
    const float* Alog = (const float*)d_in[4];
    const float* Ds   = (const float*)d_in[5];
    const float* gam  = (const float*)d_in[6];
    const float* bet  = (const float*)d_in[7];
    float* out = (float*)d_out;

    proj_kernel<<<Bn*Kn*64, 256>>>(x, xpw, dtw, dtb);
    scan_p1<<<32*NC, 192>>>(Alog);
    scan_mid<<<(32*Dn*Nn + 255)/256, 256>>>(Alog);
    scan_p2<<<32*NC, 192>>>(Alog, Ds);
    merge_ln_kernel<<<Bn*512, 256>>>(gam, bet, out);
}